// round 16
// baseline (speedup 1.0000x reference)
#include <cuda_runtime.h>
#include <math.h>
#include <stdint.h>

#define NN   100000
#define EE   640000
#define HH   128
#define EMBD 96
#define SELD 32
#define PDIM 64
#define NPOS 513
#define NT   3
#define GITERS 6

#define EPB  128
#define PADE (EE + NT*EPB)

// k_edge smem layout (bytes)
#define OF_BIAS 0
#define OF_AHI  512
#define OF_ALO  35328
#define OF_BHI  70144
#define OF_BLO  104960
#define OF_C    139776
#define SM_EDGE_BYTES 207360
#define APITCH  272
#define CPITCH  132
#define WIMGSZ  69632
#define HIMG    34816

// GRU GEMM smem layout
#define NBX     782
#define GHALF   192
#define IMGSEC  (384*APITCH)   // 104448 per hi/lo section
#define OFG_BIAS 0
#define OFG_AHI  768
#define OFG_ALO  35584
#define OFG_BHI  70400
#define OFG_BLO  122624
#define SM_G384  174848

// k_out smem layout
#define OFO_B1   0
#define OFO_W2   512
#define OFO_RED  1024
#define OFO_AHI  2048
#define OFO_ALO  36864
#define OFO_B    71680
#define SM_OUT2  210944

// ---------------- device scratch ----------------
__device__ float d_h0 [NN * HH];
__device__ float d_hA [NN * HH];
__device__ float d_hB [NN * HH];
__device__ float d_agg[NN * HH];
__device__ float d_gh [NN * 3 * HH];
__device__ float d_gtab[NPOS * HH];
__device__ float d_cnt[NN];
__device__ float d_inv[NN];
__device__ float d_bihP[384];
__device__ float d_bhhP[384];
__device__ int   d_es[PADE];
__device__ int   d_ed[PADE];
__device__ int   d_ps[PADE];
__device__ int   d_tcnt[NT];
__device__ int   d_cur[NT];
__device__ int   d_base[NT + 1];
__device__ unsigned char d_wimg[NT * WIMGSZ];
__device__ unsigned char d_gruimg[2 * 2 * IMGSEC];   // [ih|hh][hi|lo], PERMUTED col order
__device__ unsigned char d_woutimg[4 * HIMG];

__device__ __forceinline__ float sigf(float x) { return 1.0f / (1.0f + __expf(-x)); }

// permuted column map: slot j -> (gate, unit)
// 24-col blocks: [r x8 | z x8 | n x8] for 8 units; 96-col group = 32 units
__device__ __forceinline__ int pgate(int j) { return ((j % 96) % 24) >> 3; }
__device__ __forceinline__ int punit(int j) {
    int half = j / 192, rem = j % 192, grp = rem / 96, r24 = rem % 96;
    return half * 64 + grp * 32 + (r24 / 24) * 8 + (r24 % 24 & 7);
}

// ---- packed helpers ----
__device__ __forceinline__ void red4(float* p, float a, float b, float c, float d) {
    asm volatile("red.global.add.v4.f32 [%0], {%1, %2, %3, %4};"
                 :: "l"(p), "f"(a), "f"(b), "f"(c), "f"(d) : "memory");
}
__device__ __forceinline__ unsigned pkbf(float x, float y) {
    unsigned r;
    asm("cvt.rn.bf16x2.f32 %0, %1, %2;" : "=r"(r) : "f"(y), "f"(x));
    return r;
}
__device__ __forceinline__ void split2(float x, float y, unsigned& hi, unsigned& lo) {
    hi = pkbf(x, y);
    float xh = __uint_as_float(hi << 16);
    float yh = __uint_as_float(hi & 0xffff0000u);
    lo = pkbf(x - xh, y - yh);
}
__device__ __forceinline__ void mma_bf16(float c[4], const unsigned a[4], const unsigned b[2]) {
    asm volatile("mma.sync.aligned.m16n8k16.row.col.f32.bf16.bf16.f32 "
                 "{%0,%1,%2,%3}, {%4,%5,%6,%7}, {%8,%9}, {%0,%1,%2,%3};"
                 : "+f"(c[0]), "+f"(c[1]), "+f"(c[2]), "+f"(c[3])
                 : "r"(a[0]), "r"(a[1]), "r"(a[2]), "r"(a[3]), "r"(b[0]), "r"(b[1]));
}

// ---------------- setup kernels ----------------
__global__ void k_init_pad() {
    int i = blockIdx.x * blockDim.x + threadIdx.x;
    if (i < PADE) { d_ed[i] = -1; d_es[i] = 0; d_ps[i] = 0; }
    if (i < NT) { d_tcnt[i] = 0; d_cur[i] = 0; }
}
__global__ void k_hist(const int* __restrict__ et) {
    __shared__ int sc[NT];
    if (threadIdx.x < NT) sc[threadIdx.x] = 0;
    __syncthreads();
    int e = blockIdx.x * blockDim.x + threadIdx.x;
    if (e < EE) atomicAdd(&sc[et[e]], 1);
    __syncthreads();
    if (threadIdx.x < NT) atomicAdd(&d_tcnt[threadIdx.x], sc[threadIdx.x]);
}
__global__ void k_off() {
    int b = 0;
    for (int t = 0; t < NT; t++) {
        d_base[t] = b;
        b += ((d_tcnt[t] + EPB - 1) / EPB) * EPB;
    }
    d_base[NT] = b;
}
__global__ void k_perm(const int* __restrict__ src, const int* __restrict__ dst,
                       const int* __restrict__ et, const int* __restrict__ epos) {
    __shared__ int s_cnt[NT], s_base[NT];
    if (threadIdx.x < NT) s_cnt[threadIdx.x] = 0;
    __syncthreads();
    int e = blockIdx.x * blockDim.x + threadIdx.x;
    int t = 0, lr = 0;
    if (e < EE) { t = et[e]; lr = atomicAdd(&s_cnt[t], 1); }
    __syncthreads();
    if (threadIdx.x < NT) s_base[threadIdx.x] = atomicAdd(&d_cur[threadIdx.x], s_cnt[threadIdx.x]);
    __syncthreads();
    if (e < EE) {
        int p = d_base[t] + s_base[t] + lr;
        d_es[p] = src[e]; d_ed[p] = dst[e]; d_ps[p] = epos[e];
    }
}
__global__ void k_zero_cnt() {
    int i = blockIdx.x * blockDim.x + threadIdx.x;
    if (i < NN) d_cnt[i] = 0.0f;
}
__global__ void k_h0(const int* __restrict__ xidx, const float* __restrict__ sel,
                     const float* __restrict__ emb) {
    int t = blockIdx.x * blockDim.x + threadIdx.x;
    if (t >= NN * 32) return;
    int n = t >> 5, q = (t & 31) * 4;
    float4 v;
    if (q < EMBD) v = *(const float4*)&emb[(long long)xidx[n] * EMBD + q];
    else          v = *(const float4*)&sel[n * SELD + (q - EMBD)];
    *(float4*)&d_h0[n * HH + q] = v;
    *(float4*)&d_hA[n * HH + q] = v;
}
__global__ void k_deg(const int* __restrict__ dst) {
    int e = blockIdx.x * blockDim.x + threadIdx.x;
    if (e < EE) atomicAdd(&d_cnt[dst[e]], 1.0f);
}
__global__ void k_inv() {
    int i = blockIdx.x * blockDim.x + threadIdx.x;
    if (i < NN) d_inv[i] = 1.0f / fmaxf(d_cnt[i], 1.0f);
}
__global__ void k_zero_agg() {
    int i = blockIdx.x * blockDim.x + threadIdx.x;
    if (i < NN * HH / 4) ((float4*)d_agg)[i] = make_float4(0.f, 0.f, 0.f, 0.f);
}
__global__ __launch_bounds__(128) void k_gtab(const float* __restrict__ pe,
                                              const float* __restrict__ Wg,
                                              const float* __restrict__ bg) {
    __shared__ float ps[PDIM];
    int p = blockIdx.x;
    if (threadIdx.x < PDIM) ps[threadIdx.x] = pe[p * PDIM + threadIdx.x];
    __syncthreads();
    int j = threadIdx.x;
    float a = 0.0f;
    #pragma unroll 8
    for (int k = 0; k < PDIM; k++) a += ps[k] * Wg[k * HH + j];
    d_gtab[p * HH + j] = 2.0f * sigf(a + bg[j]);
}
__global__ void k_wimg(const float* __restrict__ Wt) {
    int t = blockIdx.x;
    unsigned char* wh = d_wimg + t * WIMGSZ;
    unsigned char* wl = wh + HIMG;
    for (int i = threadIdx.x; i < 128 * 64; i += blockDim.x) {
        int n = i >> 6, k = (i & 63) * 2;
        float v0 = Wt[t * HH * HH + k * HH + n];
        float v1 = Wt[t * HH * HH + (k + 1) * HH + n];
        unsigned hi, lo;
        split2(v0, v1, hi, lo);
        int o = n * APITCH + k * 2;
        *(unsigned*)(wh + o) = hi;
        *(unsigned*)(wl + o) = lo;
    }
}
// GRU weight images in PERMUTED column order + permuted biases
__global__ void k_wgru(const float* __restrict__ Wih, const float* __restrict__ Whh,
                       const float* __restrict__ bih, const float* __restrict__ bhh) {
    int m = blockIdx.y;
    const float* W = m ? Whh : Wih;
    unsigned char* wh = d_gruimg + m * 2 * IMGSEC;
    unsigned char* wl = wh + IMGSEC;
    for (int i = blockIdx.x * blockDim.x + threadIdx.x; i < 384 * 64; i += gridDim.x * blockDim.x) {
        int j = i >> 6, k = (i & 63) * 2;
        int lrow = pgate(j) * 128 + punit(j);
        unsigned hi, lo;
        split2(W[lrow * 128 + k], W[lrow * 128 + k + 1], hi, lo);
        int o = j * APITCH + k * 2;
        *(unsigned*)(wh + o) = hi;
        *(unsigned*)(wl + o) = lo;
    }
    if (blockIdx.x == 0 && threadIdx.x < 384) {
        int j = threadIdx.x;
        int lrow = pgate(j) * 128 + punit(j);
        if (m) d_bhhP[j] = bhh[lrow];
        else   d_bihP[j] = bih[lrow];
    }
}
__global__ void k_wout(const float* __restrict__ W1) {
    int hf = blockIdx.y;
    unsigned char* wh = d_woutimg + hf * 2 * HIMG;
    unsigned char* wl = wh + HIMG;
    for (int i = blockIdx.x * blockDim.x + threadIdx.x; i < 128 * 64; i += gridDim.x * blockDim.x) {
        int j = i >> 6, kk = (i & 63) * 2;
        int k = hf * 128 + kk;
        unsigned hi, lo;
        split2(W1[k * 128 + j], W1[(k + 1) * 128 + j], hi, lo);
        int o = j * APITCH + kk * 2;
        *(unsigned*)(wh + o) = hi;
        *(unsigned*)(wl + o) = lo;
    }
}

// ---------------- edge phase: persistent HMMA bf16x3 (unchanged) ----------------
__global__ __launch_bounds__(256) void k_edge(const float* __restrict__ bt, int flip) {
    extern __shared__ char smc[];
    int tid = threadIdx.x, wid = tid >> 5, lane = tid & 31;
    const float* __restrict__ h = flip ? d_hB : d_hA;
    int b1v = d_base[1], b2v = d_base[2];
    int ntiles = d_base[NT] >> 7;
    int tpb = (ntiles + 147) / 148;
    int t0 = blockIdx.x * tpb;
    int t1 = t0 + tpb;
    if (t1 > ntiles) t1 = ntiles;
    int cur = -1;

    int g = lane >> 2, tg = lane & 3;
    int rb = (wid >> 1) * 32, cb = (wid & 1) * 64;
    float* Cb = (float*)(smc + OF_C);

    for (int tile = t0; tile < t1; tile++) {
        int start = tile << 7;
        int t = (start >= b1v) + (start >= b2v);
        if (t != cur) {
            cur = t;
            const uint4* sp = (const uint4*)(d_wimg + t * WIMGSZ);
            uint4* dp = (uint4*)(smc + OF_BHI);
            for (int i = tid; i < WIMGSZ / 16; i += 256) dp[i] = sp[i];
            if (tid < 128) *(float*)(smc + OF_BIAS + 4 * tid) = bt[t * HH + tid];
        }
        {
            int r = tid >> 1, kb = (tid & 1) * 64;
            int s = d_es[start + r], pp = d_ps[start + r];
            const float4* hv = (const float4*)&h[s * HH + kb];
            const float4* gv = (const float4*)&d_gtab[pp * HH + kb];
            char* arh = smc + OF_AHI + r * APITCH + kb * 2;
            char* arl = smc + OF_ALO + r * APITCH + kb * 2;
            #pragma unroll 4
            for (int i = 0; i < 16; i++) {
                float4 a = hv[i], gg = gv[i];
                unsigned h0, l0, h1, l1;
                split2(a.x * gg.x, a.y * gg.y, h0, l0);
                split2(a.z * gg.z, a.w * gg.w, h1, l1);
                *(uint2*)(arh + i * 8) = make_uint2(h0, h1);
                *(uint2*)(arl + i * 8) = make_uint2(l0, l1);
            }
        }
        __syncthreads();

        float c[2][8][4];
        #pragma unroll
        for (int mt = 0; mt < 2; mt++)
            #pragma unroll
            for (int nt = 0; nt < 8; nt++)
                #pragma unroll
                for (int q = 0; q < 4; q++) c[mt][nt][q] = 0.0f;

        #pragma unroll
        for (int p = 0; p < 3; p++) {
            const char* Ab = smc + ((p < 2) ? OF_AHI : OF_ALO);
            const char* Bb = smc + ((p == 1) ? OF_BLO : OF_BHI);
            #pragma unroll
            for (int ks = 0; ks < 8; ks++) {
                int koff = (ks * 16 + tg * 2) * 2;
                unsigned a[2][4], b[8][2];
                #pragma unroll
                for (int mt = 0; mt < 2; mt++) {
                    const char* ar = Ab + (rb + mt * 16 + g) * APITCH + koff;
                    a[mt][0] = *(const unsigned*)(ar);
                    a[mt][1] = *(const unsigned*)(ar + 8 * APITCH);
                    a[mt][2] = *(const unsigned*)(ar + 16);
                    a[mt][3] = *(const unsigned*)(ar + 8 * APITCH + 16);
                }
                #pragma unroll
                for (int nt = 0; nt < 8; nt++) {
                    const char* br = Bb + (cb + nt * 8 + g) * APITCH + koff;
                    b[nt][0] = *(const unsigned*)(br);
                    b[nt][1] = *(const unsigned*)(br + 16);
                }
                #pragma unroll
                for (int mt = 0; mt < 2; mt++)
                    #pragma unroll
                    for (int nt = 0; nt < 8; nt++)
                        mma_bf16(c[mt][nt], a[mt], b[nt]);
            }
        }

        #pragma unroll
        for (int mt = 0; mt < 2; mt++)
            #pragma unroll
            for (int nt = 0; nt < 8; nt++) {
                int row = rb + mt * 16 + g, col = cb + nt * 8 + tg * 2;
                *(float2*)&Cb[row * CPITCH + col]       = make_float2(c[mt][nt][0], c[mt][nt][1]);
                *(float2*)&Cb[(row + 8) * CPITCH + col] = make_float2(c[mt][nt][2], c[mt][nt][3]);
            }
        __syncthreads();

        {
            int r = tid >> 1, c0 = (tid & 1) * 64;
            int d = d_ed[start + r];
            if (d >= 0) {
                float invd = d_inv[d];
                #pragma unroll 4
                for (int j = 0; j < 16; j++) {
                    float4 v  = *(float4*)&Cb[r * CPITCH + c0 + 4 * j];
                    float4 bb = *(float4*)(smc + OF_BIAS + 4 * (c0 + 4 * j));
                    red4(&d_agg[d * HH + c0 + 4 * j],
                         (v.x + bb.x) * invd, (v.y + bb.y) * invd,
                         (v.z + bb.z) * invd, (v.w + bb.w) * invd);
                }
            }
        }
    }
}

// ---------------- hh GEMM: d_gh = h @ W_hh^T + b_hh (permuted slots) ----------------
__global__ __launch_bounds__(256) void k_ghh(int flip) {
    extern __shared__ char smc[];
    int tid = threadIdx.x, wid = tid >> 5, lane = tid & 31;
    int n0 = blockIdx.x * 128;
    int half = blockIdx.y;
    const float* __restrict__ A = flip ? d_hB : d_hA;
    const unsigned char* img = d_gruimg + 2 * IMGSEC;   // hh section

    if (tid < GHALF) *(float*)(smc + OFG_BIAS + 4 * tid) = d_bhhP[half * GHALF + tid];

    if (tid < 128) {
        int r = tid, n = n0 + r;
        char* arh = smc + OFG_AHI + r * APITCH;
        char* arl = smc + OFG_ALO + r * APITCH;
        if (n < NN) {
            const float4* av = (const float4*)&A[n * HH];
            #pragma unroll 8
            for (int i = 0; i < 32; i++) {
                float4 a = av[i];
                unsigned h0, l0, h1, l1;
                split2(a.x, a.y, h0, l0);
                split2(a.z, a.w, h1, l1);
                *(uint2*)(arh + i * 8) = make_uint2(h0, h1);
                *(uint2*)(arl + i * 8) = make_uint2(l0, l1);
            }
        } else {
            #pragma unroll 8
            for (int i = 0; i < 32; i++) {
                *(uint2*)(arh + i * 8) = make_uint2(0u, 0u);
                *(uint2*)(arl + i * 8) = make_uint2(0u, 0u);
            }
        }
    } else {
        int idx = tid - 128;
        const uint4* sph = (const uint4*)(img + half * GHALF * APITCH);
        const uint4* spl = (const uint4*)(img + IMGSEC + half * GHALF * APITCH);
        uint4* dph = (uint4*)(smc + OFG_BHI);
        uint4* dpl = (uint4*)(smc + OFG_BLO);
        for (int i = idx; i < GHALF * APITCH / 16; i += 128) { dph[i] = sph[i]; dpl[i] = spl[i]; }
    }
    __syncthreads();

    int g = lane >> 2, tg = lane & 3;
    int rb = (wid & 3) * 32, cb = (wid >> 2) * 96;
    float c[2][12][4];
    #pragma unroll
    for (int mt = 0; mt < 2; mt++)
        #pragma unroll
        for (int nt = 0; nt < 12; nt++)
            #pragma unroll
            for (int q = 0; q < 4; q++) c[mt][nt][q] = 0.0f;

    #pragma unroll
    for (int p = 0; p < 3; p++) {
        const char* Ab = smc + ((p < 2) ? OFG_AHI : OFG_ALO);
        const char* Bb = smc + ((p == 1) ? OFG_BLO : OFG_BHI);
        #pragma unroll
        for (int ks = 0; ks < 8; ks++) {
            int koff = (ks * 16 + tg * 2) * 2;
            unsigned a[2][4], b[12][2];
            #pragma unroll
            for (int mt = 0; mt < 2; mt++) {
                const char* ar = Ab + (rb + mt * 16 + g) * APITCH + koff;
                a[mt][0] = *(const unsigned*)(ar);
                a[mt][1] = *(const unsigned*)(ar + 8 * APITCH);
                a[mt][2] = *(const unsigned*)(ar + 16);
                a[mt][3] = *(const unsigned*)(ar + 8 * APITCH + 16);
            }
            #pragma unroll
            for (int nt = 0; nt < 12; nt++) {
                const char* br = Bb + (cb + nt * 8 + g) * APITCH + koff;
                b[nt][0] = *(const unsigned*)(br);
                b[nt][1] = *(const unsigned*)(br + 16);
            }
            #pragma unroll
            for (int mt = 0; mt < 2; mt++)
                #pragma unroll
                for (int nt = 0; nt < 12; nt++)
                    mma_bf16(c[mt][nt], a[mt], b[nt]);
        }
    }

    #pragma unroll
    for (int mt = 0; mt < 2; mt++) {
        int row = rb + mt * 16 + g;
        int n1 = n0 + row, n2 = n1 + 8;
        #pragma unroll
        for (int nt = 0; nt < 12; nt++) {
            int col = cb + nt * 8 + tg * 2;
            float2 bb = *(float2*)(smc + OFG_BIAS + 4 * col);
            int gcol = half * GHALF + col;
            if (n1 < NN)
                *(float2*)&d_gh[n1 * 384 + gcol] = make_float2(c[mt][nt][0] + bb.x, c[mt][nt][1] + bb.y);
            if (n2 < NN)
                *(float2*)&d_gh[n2 * 384 + gcol] = make_float2(c[mt][nt][2] + bb.x, c[mt][nt][3] + bb.y);
        }
    }
}

// ---------------- fused ih GEMM + GRU combine: gi in regs, h' out ----------------
__global__ __launch_bounds__(256) void k_gic(int flip) {
    extern __shared__ char smc[];
    int tid = threadIdx.x, wid = tid >> 5, lane = tid & 31;
    int n0 = blockIdx.x * 128;
    int half = blockIdx.y;
    const float* __restrict__ h = flip ? d_hB : d_hA;
    float* __restrict__ hn      = flip ? d_hA : d_hB;
    const unsigned char* img = d_gruimg;   // ih section

    if (tid < GHALF) *(float*)(smc + OFG_BIAS + 4 * tid) = d_bihP[half * GHALF + tid];

    if (tid < 128) {
        int r = tid, n = n0 + r;
        char* arh = smc + OFG_AHI + r * APITCH;
        char* arl = smc + OFG_ALO + r * APITCH;
        if (n < NN) {
            const float4* av = (const float4*)&d_agg[n * HH];
            #pragma unroll 8
            for (int i = 0; i < 32; i++) {
                float4 a = av[i];
                unsigned h0, l0, h1, l1;
                split2(a.x, a.y, h0, l0);
                split2(a.z, a.w, h1, l1);
                *(uint2*)(arh + i * 8) = make_uint2(h0, h1);
                *(uint2*)(arl + i * 8) = make_uint2(l0, l1);
            }
        } else {
            #pragma unroll 8
            for (int i = 0; i < 32; i++) {
                *(uint2*)(arh + i * 8) = make_uint2(0u, 0u);
                *(uint2*)(arl + i * 8) = make_uint2(0u, 0u);
            }
        }
    } else {
        int idx = tid - 128;
        const uint4* sph = (const uint4*)(img + half * GHALF * APITCH);
        const uint4* spl = (const uint4*)(img + IMGSEC + half * GHALF * APITCH);
        uint4* dph = (uint4*)(smc + OFG_BHI);
        uint4* dpl = (uint4*)(smc + OFG_BLO);
        for (int i = idx; i < GHALF * APITCH / 16; i += 128) { dph[i] = sph[i]; dpl[i] = spl[i]; }
    }
    __syncthreads();

    int g = lane >> 2, tg = lane & 3;
    int rb = (wid & 3) * 32, cb = (wid >> 2) * 96;
    float c[2][12][4];
    #pragma unroll
    for (int mt = 0; mt < 2; mt++)
        #pragma unroll
        for (int nt = 0; nt < 12; nt++)
            #pragma unroll
            for (int q = 0; q < 4; q++) c[mt][nt][q] = 0.0f;

    #pragma unroll
    for (int p = 0; p < 3; p++) {
        const char* Ab = smc + ((p < 2) ? OFG_AHI : OFG_ALO);
        const char* Bb = smc + ((p == 1) ? OFG_BLO : OFG_BHI);
        #pragma unroll
        for (int ks = 0; ks < 8; ks++) {
            int koff = (ks * 16 + tg * 2) * 2;
            unsigned a[2][4], b[12][2];
            #pragma unroll
            for (int mt = 0; mt < 2; mt++) {
                const char* ar = Ab + (rb + mt * 16 + g) * APITCH + koff;
                a[mt][0] = *(const unsigned*)(ar);
                a[mt][1] = *(const unsigned*)(ar + 8 * APITCH);
                a[mt][2] = *(const unsigned*)(ar + 16);
                a[mt][3] = *(const unsigned*)(ar + 8 * APITCH + 16);
            }
            #pragma unroll
            for (int nt = 0; nt < 12; nt++) {
                const char* br = Bb + (cb + nt * 8 + g) * APITCH + koff;
                b[nt][0] = *(const unsigned*)(br);
                b[nt][1] = *(const unsigned*)(br + 16);
            }
            #pragma unroll
            for (int mt = 0; mt < 2; mt++)
                #pragma unroll
                for (int nt = 0; nt < 12; nt++)
                    mma_bf16(c[mt][nt], a[mt], b[nt]);
        }
    }

    // fused GRU combine: this thread's 12 col-fragments = 4 complete (r,z,n) triples
    #pragma unroll
    for (int mt = 0; mt < 2; mt++) {
        int row = rb + mt * 16 + g;
        #pragma unroll
        for (int m = 0; m < 4; m++) {
            int colr = cb + 24 * m + tg * 2;
            int js = half * GHALF + colr;                  // slot of r pair
            float2 br = *(float2*)(smc + OFG_BIAS + 4 * colr);
            float2 bz = *(float2*)(smc + OFG_BIAS + 4 * (colr + 8));
            float2 bn = *(float2*)(smc + OFG_BIAS + 4 * (colr + 16));
            int u = half * 64 + (cb ? 32 : 0) + m * 8 + tg * 2;
            #pragma unroll
            for (int hlf = 0; hlf < 2; hlf++) {
                int n = n0 + row + hlf * 8;
                if (n >= NN) continue;
                float gir0 = c[mt][3 * m + 0][2 * hlf + 0] + br.x;
                float gir1 = c[mt][3 * m + 0][2 * hlf + 1] + br.y;
                float giz0 = c[mt][3 * m + 1][2 * hlf + 0] + bz.x;
                float giz1 = c[mt][3 * m + 1][2 * hlf + 1] + bz.y;
                float gin0 = c[mt][3 * m + 2][2 * hlf + 0] + bn.x;
                float gin1 = c[mt][3 * m + 2][2 * hlf + 1] + bn.y;
                const float* ghp = &d_gh[n * 384 + js];
                float2 ghr = *(const float2*)(ghp);
                float2 ghz = *(const float2*)(ghp + 8);
                float2 ghn = *(const float2*)(ghp + 16);
                float2 hv  = *(const float2*)&h[n * HH + u];
                float r0 = sigf(gir0 + ghr.x), r1 = sigf(gir1 + ghr.y);
                float z0 = sigf(giz0 + ghz.x), z1 = sigf(giz1 + ghz.y);
                float nn0 = tanhf(gin0 + r0 * ghn.x);
                float nn1 = tanhf(gin1 + r1 * ghn.y);
                float o0 = (1.0f - z0) * nn0 + z0 * hv.x;
                float o1 = (1.0f - z1) * nn1 + z1 * hv.y;
                *(float2*)&hn[n * HH + u] = make_float2(o0, o1);
            }
        }
    }
}

// ---------------- output head: HMMA bf16x3 (R15 version, unchanged) ----------------
__global__ __launch_bounds__(256) void k_out(const float* __restrict__ b1,
                                             const float* __restrict__ W2,
                                             const float* __restrict__ b2,
                                             float* __restrict__ out) {
    extern __shared__ char smc[];
    int tid = threadIdx.x, wid = tid >> 5, lane = tid & 31;
    int n0 = blockIdx.x * 128;

    if (tid < 128) {
        *(float*)(smc + OFO_B1 + 4 * tid) = b1[tid];
        *(float*)(smc + OFO_W2 + 4 * tid) = W2[tid];
    }
    {
        const uint4* sp = (const uint4*)d_woutimg;
        uint4* dp = (uint4*)(smc + OFO_B);
        for (int i = tid; i < 4 * HIMG / 16; i += 256) dp[i] = sp[i];
    }

    int g = lane >> 2, tg = lane & 3;
    int rb = (wid >> 1) * 32, cb = (wid & 1) * 64;
    float c[2][8][4];
    #pragma unroll
    for (int mt = 0; mt < 2; mt++)
        #pragma unroll
        for (int nt = 0; nt < 8; nt++)
            #pragma unroll
            for (int q = 0; q < 4; q++) c[mt][nt][q] = 0.0f;

    #pragma unroll
    for (int hf = 0; hf < 2; hf++) {
        const float* __restrict__ A = hf ? d_h0 : d_hA;
        {
            int r = tid >> 1, kb = (tid & 1) * 64;
            int n = n0 + r;
            char* arh = smc + OFO_AHI + r * APITCH + kb * 2;
            char* arl = smc + OFO_ALO + r * APITCH + kb * 2;
            if (n < NN) {
                const float4* av = (const float4*)&A[n * HH + kb];
                #pragma unroll 4
                for (int i = 0; i < 16; i++) {
                    float4 a = av[i];
                    unsigned h0, l0, h1, l1;
                    split2(a.x, a.y, h0, l0);
                    split2(a.z, a.w, h1, l1);
                    *(uint2*)(arh + i * 8) = make_uint2(h0, h1);
                    *(uint2*)(arl + i * 8) = make_uint2(l0, l1);
                }
            } else {
                #pragma unroll 4
                for (int i = 0; i < 16; i++) {
                    *(uint2*)(arh + i * 8) = make_uint2(0u, 0u);
                    *(uint2*)(arl + i * 8) = make_uint2(0u, 0u);
                }
            }
        }
        __syncthreads();

        const char* Bh = smc + OFO_B + hf * 2 * HIMG;
        #pragma unroll
        for (int p = 0; p < 3; p++) {
            const char* Ab = smc + ((p < 2) ? OFO_AHI : OFO_ALO);
            const char* Bb = Bh + ((p == 1) ? HIMG : 0);
            #pragma unroll
            for (int ks = 0; ks < 8; ks++) {
                int koff = (ks * 16 + tg * 2) * 2;
                unsigned a[2][4], b[8][2];
                #pragma unroll
                for (int mt = 0; mt < 2; mt++) {
                    const char* ar = Ab + (rb + mt * 16 + g) * APITCH + koff;
                    a[mt][0] = *(const unsigned*)(ar);
                    a[mt][1] = *(const unsigned*)(ar + 8 * APITCH);
                    a[mt][2] = *(const unsigned*)(ar + 16);
                    a[mt][3] = *(const unsigned*)(ar + 8 * APITCH + 16);
                }
                #pragma unroll
                for (int nt = 0; nt < 8; nt++) {
                    const char* br = Bb + (cb + nt * 8 + g) * APITCH + koff;
                    b[nt][0] = *(const unsigned*)(br);
                    b[nt][1] = *(const unsigned*)(br + 16);
                }
                #pragma unroll
                for (int mt = 0; mt < 2; mt++)
                    #pragma unroll
                    for (int nt = 0; nt < 8; nt++)
                        mma_bf16(c[mt][nt], a[mt], b[nt]);
            }
        }
        __syncthreads();
    }

    float part[2][2];
    #pragma unroll
    for (int mt = 0; mt < 2; mt++) { part[mt][0] = 0.f; part[mt][1] = 0.f; }
    #pragma unroll
    for (int mt = 0; mt < 2; mt++)
        #pragma unroll
        for (int nt = 0; nt < 8; nt++) {
            int col = cb + nt * 8 + tg * 2;
            float2 bb = *(float2*)(smc + OFO_B1 + 4 * col);
            float2 w2 = *(float2*)(smc + OFO_W2 + 4 * col);
            #pragma unroll
            for (int hlf = 0; hlf < 2; hlf++) {
                float v0 = fmaxf(c[mt][nt][2 * hlf + 0] + bb.x, 0.f);
                float v1 = fmaxf(c[mt][nt][2 * hlf + 1] + bb.y, 0.f);
                part[mt][hlf] += v0 * w2.x + v1 * w2.y;
            }
        }
    #pragma unroll
    for (int mt = 0; mt < 2; mt++)
        #pragma unroll
        for (int hlf = 0; hlf < 2; hlf++) {
            float p = part[mt][hlf];
            p += __shfl_xor_sync(0xFFFFFFFFu, p, 1);
            p += __shfl_xor_sync(0xFFFFFFFFu, p, 2);
            part[mt][hlf] = p;
        }
    if (tg == 0) {
        float* red = (float*)(smc + OFO_RED);
        #pragma unroll
        for (int mt = 0; mt < 2; mt++)
            #pragma unroll
            for (int hlf = 0; hlf < 2; hlf++) {
                int row = rb + mt * 16 + g + hlf * 8;
                red[row * 2 + (wid & 1)] = part[mt][hlf];
            }
    }
    __syncthreads();
    if (tid < 128) {
        int n = n0 + tid;
        if (n < NN) {
            const float* red = (const float*)(smc + OFO_RED);
            out[n] = red[tid * 2] + red[tid * 2 + 1] + b2[0];
        }
    }
}

// ---------------- launch ----------------
extern "C" void kernel_launch(void* const* d_in, const int* in_sizes, int n_in,
                              void* d_out, int out_size) {
    (void)in_sizes; (void)n_in; (void)out_size;
    const int*   xidx = (const int*)  d_in[0];
    const float* sel  = (const float*)d_in[1];
    const int*   eidx = (const int*)  d_in[2];
    const int*   et   = (const int*)  d_in[3];
    const int*   epos = (const int*)  d_in[4];
    const float* emb  = (const float*)d_in[5];
    const float* pe   = (const float*)d_in[6];
    const float* Wg   = (const float*)d_in[7];
    const float* bg   = (const float*)d_in[8];
    const float* Wt   = (const float*)d_in[9];
    const float* bt   = (const float*)d_in[10];
    const float* Wih  = (const float*)d_in[11];
    const float* Whh  = (const float*)d_in[12];
    const float* bih  = (const float*)d_in[13];
    const float* bhh  = (const float*)d_in[14];
    const float* W1   = (const float*)d_in[15];
    const float* b1   = (const float*)d_in[16];
    const float* W2   = (const float*)d_in[17];
    const float* b2   = (const float*)d_in[18];
    float* out = (float*)d_out;
    const int* src = eidx;
    const int* dst = eidx + EE;

    cudaFuncSetAttribute(k_edge, cudaFuncAttributeMaxDynamicSharedMemorySize, SM_EDGE_BYTES);
    cudaFuncSetAttribute(k_ghh,  cudaFuncAttributeMaxDynamicSharedMemorySize, SM_G384);
    cudaFuncSetAttribute(k_gic,  cudaFuncAttributeMaxDynamicSharedMemorySize, SM_G384);
    cudaFuncSetAttribute(k_out,  cudaFuncAttributeMaxDynamicSharedMemorySize, SM_OUT2);

    k_init_pad<<<(PADE + 255) / 256, 256>>>();
    k_hist<<<(EE + 255) / 256, 256>>>(et);
    k_off<<<1, 1>>>();
    k_perm<<<(EE + 255) / 256, 256>>>(src, dst, et, epos);
    k_zero_cnt<<<(NN + 255) / 256, 256>>>();
    k_h0<<<(NN * 32 + 255) / 256, 256>>>(xidx, sel, emb);
    k_deg<<<(EE + 255) / 256, 256>>>(dst);
    k_inv<<<(NN + 255) / 256, 256>>>();
    k_gtab<<<NPOS, 128>>>(pe, Wg, bg);
    k_wimg<<<NT, 256>>>(Wt);
    k_wgru<<<dim3(96, 2), 256>>>(Wih, Whh, bih, bhh);
    k_wout<<<dim3(32, 2), 256>>>(W1);

    dim3 ggrid(NBX, 2);
    for (int it = 0; it < GITERS; it++) {
        int flip = it & 1;
        k_zero_agg<<<(NN * HH / 4 + 255) / 256, 256>>>();
        k_edge<<<148, 256, SM_EDGE_BYTES>>>(bt, flip);
        k_ghh<<<ggrid, 256, SM_G384>>>(flip);
        k_gic<<<ggrid, 256, SM_G384>>>(flip);
    }
    k_out<<<NBX, 256, SM_OUT2>>>(b1, W2, b2, out);
}